// round 5
// baseline (speedup 1.0000x reference)
#include <cuda_runtime.h>
#include <cuda_bf16.h>
#include <cstdint>
#include <cstdio>
#include <math.h>

#define B_   64
#define S_   512
#define E_   256
#define H_   256
#define NT_  24
#define M_   (S_ * B_)   // 32768

// ---------------------------------------------------------------------------
// Device-global scratch (allocation-free rule). All scalar-accessed.
// ---------------------------------------------------------------------------
__device__ float g_xW[2048ll * 32768ll];           // [n = dir*1024+gate*256+u][m = t*64+b]
__device__ float g_h[2][2][256][64];               // [dir][pingpong][unit][b]
__device__ float g_c[2][256][64];                  // [dir][unit][b]
__device__ float g_hall[512ll * 512ll * 64ll];     // [t][c = dir*256+u][b]
__device__ float g_emis[(long long)S_ * B_ * NT_]; // [t][b][tag]
__device__ int   g_maskmode;                       // 0=u8 1=i32 2=f32 3=bf16 4=all-true

__device__ __forceinline__ float sigm(float x) { return 1.0f / (1.0f + expf(-x)); }

__device__ __forceinline__ bool read_mask(const void* m, int i, int mode) {
    switch (mode) {
        case 0:  return ((const unsigned char*)m)[i] != 0;
        case 1:  return ((const int*)m)[i] != 0;
        case 2:  return ((const float*)m)[i] != 0.0f;
        case 3:  return ((const unsigned short*)m)[i] != 0;
        default: return true;
    }
}

// ---------------------------------------------------------------------------
// init: zero h ping-pong + c, detect mask dtype.
// ---------------------------------------------------------------------------
__global__ void init_kernel(const unsigned* __restrict__ mask_words, int have_mask)
{
    int i = blockIdx.x * 256 + threadIdx.x;
    if (i < 2 * 2 * 256 * 64) (&g_h[0][0][0][0])[i] = 0.0f;
    if (i < 2 * 256 * 64)     (&g_c[0][0][0])[i]    = 0.0f;
    if (i == 0) {
        // mask[0][0..3] are all True by construction (lengths >= 256).
        int mode = 4;
        if (have_mask) {
            unsigned w = mask_words[0];
            if (w == 1u)               mode = 1;
            else if (w == 0x3F800000u) mode = 2;
            else if (w == 0x3F803F80u) mode = 3;
            else                       mode = 0;
        }
        g_maskmode = mode;
    }
}

// ---------------------------------------------------------------------------
// GEMM (simple, scalar): xW[n][m] = sum_k Wih_row_n[k] * emb[tok(m)][k]
// ---------------------------------------------------------------------------
__global__ void __launch_bounds__(256) gemm_simple(const int* __restrict__ x,
                                                   const float* __restrict__ emb,
                                                   const float* __restrict__ Wf,
                                                   const float* __restrict__ Wb)
{
    __shared__ float es[128][65];
    __shared__ float Ws[16][128];
    __shared__ int   tok[64];

    const int tid = threadIdx.x;
    const int m0  = blockIdx.x * 64;
    const int n0  = blockIdx.y * 16;
    const float* W = (n0 < 1024) ? (Wf + (size_t)n0 * E_)
                                 : (Wb + (size_t)(n0 - 1024) * E_);

    if (tid < 64) {
        int m = m0 + tid;
        int tk = x[(m & 63) * S_ + (m >> 6)];      // x[b][t], b=m&63, t=m>>6
        tok[tid] = min(max(tk, 0), 50000);         // defensive clamp
    }
    __syncthreads();

    const int j  = tid >> 6;     // 0..3 row subtile
    const int ml = tid & 63;     // m within tile

    float acc[4] = {0.0f, 0.0f, 0.0f, 0.0f};

    for (int kh = 0; kh < 2; ++kh) {
        for (int idx = tid; idx < 64 * 128; idx += 256) {
            int mm = idx >> 7;
            int kk = idx & 127;
            es[kk][mm] = emb[(size_t)tok[mm] * E_ + kh * 128 + kk];
        }
        for (int idx = tid; idx < 16 * 128; idx += 256) {
            int r  = idx >> 7;
            int kk = idx & 127;
            Ws[r][kk] = W[(size_t)r * E_ + kh * 128 + kk];
        }
        __syncthreads();

        for (int kk = 0; kk < 128; ++kk) {
            float hv = es[kk][ml];
#pragma unroll
            for (int rr = 0; rr < 4; ++rr)
                acc[rr] = fmaf(Ws[j * 4 + rr][kk], hv, acc[rr]);
        }
        __syncthreads();
    }

#pragma unroll
    for (int rr = 0; rr < 4; ++rr) {
        int n = n0 + j * 4 + rr;
        g_xW[(size_t)n * M_ + m0 + ml] = acc[rr];
    }
}

// ---------------------------------------------------------------------------
// One LSTM timestep, both directions. grid = 128 blocks x 256 threads.
// gates: ((xW + hW) + bih) + bhh   (reference association order)
// ---------------------------------------------------------------------------
__global__ void __launch_bounds__(256) step_kernel(int s,
                                                   const float* __restrict__ Whf,
                                                   const float* __restrict__ Whb,
                                                   const float* __restrict__ bihf,
                                                   const float* __restrict__ bhhf,
                                                   const float* __restrict__ bihb,
                                                   const float* __restrict__ bhhb)
{
    __shared__ float Whs[16][256];   // [gate*4 + j][k]
    __shared__ float hs[64][65];     // h chunk [k_local][b]

    const int tid = threadIdx.x;
    const int dir = blockIdx.x >> 6;
    const int us  = (blockIdx.x & 63) * 4;
    const int j   = tid >> 6;
    const int b   = tid & 63;
    const int u   = us + j;

    const float* Wh  = dir ? Whb : Whf;
    const float* bih = dir ? bihb : bihf;
    const float* bhh = dir ? bhhb : bhhf;

    const int t  = dir ? (S_ - 1 - s) : s;
    const int rb = s & 1, wbuf = rb ^ 1;

    for (int idx = tid; idx < 16 * 256; idx += 256) {
        int r  = idx >> 8;           // 0..15 = gate*4 + jj
        int kk = idx & 255;
        Whs[r][kk] = Wh[(size_t)((r >> 2) * 256 + us + (r & 3)) * 256 + kk];
    }

    float acc[4] = {0.0f, 0.0f, 0.0f, 0.0f};

    for (int kc = 0; kc < 4; ++kc) {
        __syncthreads();
        for (int idx = tid; idx < 64 * 64; idx += 256) {
            int kk = idx >> 6;
            int bb = idx & 63;
            hs[kk][bb] = g_h[dir][rb][kc * 64 + kk][bb];
        }
        __syncthreads();

        for (int kk = 0; kk < 64; ++kk) {
            float hv = hs[kk][b];
#pragma unroll
            for (int g = 0; g < 4; ++g)
                acc[g] = fmaf(Whs[g * 4 + j][kc * 64 + kk], hv, acc[g]);
        }
    }

    float gv[4];
#pragma unroll
    for (int g = 0; g < 4; ++g) {
        float xw = g_xW[(size_t)(dir * 1024 + g * 256 + u) * M_ + t * 64 + b];
        gv[g] = ((xw + acc[g]) + bih[g * 256 + u]) + bhh[g * 256 + u];
    }

    float cprev = g_c[dir][u][b];
    float c = sigm(gv[1]) * cprev + sigm(gv[0]) * tanhf(gv[2]);
    float h = sigm(gv[3]) * tanhf(c);

    g_c[dir][u][b]       = c;
    g_h[dir][wbuf][u][b] = h;
    g_hall[((size_t)t * 512 + dir * 256 + u) * 64 + b] = h;
}

// ---------------------------------------------------------------------------
// Emission: thread per (t,b). grid 128 x 256.
// ---------------------------------------------------------------------------
__global__ void __launch_bounds__(256) emis_kernel(const float* __restrict__ Wout,
                                                   const float* __restrict__ bout)
{
    const int gid = blockIdx.x * 256 + threadIdx.x;
    const int t = gid >> 6, b = gid & 63;

    float acc[NT_];
#pragma unroll
    for (int jj = 0; jj < NT_; ++jj) acc[jj] = 0.0f;

    const float* hp = g_hall + (size_t)t * 512 * 64 + b;
    for (int k = 0; k < 512; ++k) {
        float hv = hp[(size_t)k * 64];
#pragma unroll
        for (int jj = 0; jj < NT_; ++jj)
            acc[jj] = fmaf(hv, Wout[jj * 512 + k], acc[jj]);
    }

    float* op = g_emis + (size_t)(t * 64 + b) * NT_;
#pragma unroll
    for (int jj = 0; jj < NT_; ++jj) op[jj] = acc[jj] + bout[jj];
}

// ---------------------------------------------------------------------------
// Viterbi: one block per batch. Output written as FLOAT tags.
// ---------------------------------------------------------------------------
__global__ void viterbi_kernel(const void* __restrict__ mask,
                               const float* __restrict__ trans,
                               const float* __restrict__ startv,
                               const float* __restrict__ endv,
                               float* __restrict__ out)
{
    __shared__ float tr[24][25];
    __shared__ float sc[2][24];
    __shared__ unsigned char bp[511][24];
    __shared__ int tagseq[512];

    const int b   = blockIdx.x;
    const int tid = threadIdx.x;
    const int mode = g_maskmode;

    for (int f = tid; f < 576; f += 32) tr[f / 24][f % 24] = trans[f];
    if (tid < 24) sc[0][tid] = startv[tid] + g_emis[(size_t)b * NT_ + tid];
    __syncwarp();

    for (int t = 1; t < S_; ++t) {
        int pr = (t - 1) & 1, nx = t & 1;
        if (tid < 24) {
            float e = g_emis[((size_t)t * 64 + b) * NT_ + tid];
            float best = (sc[pr][0] + tr[0][tid]) + e;
            int bi = 0;
#pragma unroll
            for (int i = 1; i < 24; ++i) {
                float v = (sc[pr][i] + tr[i][tid]) + e;
                if (v > best) { best = v; bi = i; }
            }
            if (read_mask(mask, b * S_ + t, mode)) {
                sc[nx][tid]    = best;
                bp[t - 1][tid] = (unsigned char)bi;
            } else {
                sc[nx][tid]    = sc[pr][tid];
                bp[t - 1][tid] = (unsigned char)tid;
            }
        }
        __syncwarp();
    }

    if (tid == 0) {
        float best = sc[1][0] + endv[0];
        int bi = 0;
        for (int i = 1; i < 24; ++i) {
            float v = sc[1][i] + endv[i];
            if (v > best) { best = v; bi = i; }
        }
        int cur = bi;
        tagseq[511] = cur;
        for (int t = 511; t >= 1; --t) {
            cur = bp[t - 1][cur];
            tagseq[t - 1] = cur;
        }
    }
    __syncthreads();
    for (int t = tid; t < S_; t += 32) out[b * S_ + t] = (float)tagseq[t];
}

// ---------------------------------------------------------------------------
// diag: one thread, prints pipeline state samples (shows up in failure log).
// ---------------------------------------------------------------------------
__global__ void diag_kernel(const int* __restrict__ x, const float* __restrict__ emb,
                            const float* __restrict__ out)
{
    if (blockIdx.x != 0 || threadIdx.x != 0) return;
    int nbad = 0;
    for (int i = 0; i < 512; ++i)
        if (!isfinite(g_xW[(size_t)i * 131071ll])) nbad++;
    int hbad = 0;
    for (int i = 0; i < 512; ++i)
        if (!isfinite(g_hall[(size_t)i * 32749ll])) hbad++;
    printf("DIAG mm=%d x0=%d x1=%d xl=%d emb0=%.3e xW0=%.3e xWbad=%d hall0=%.3e hbad=%d "
           "em0=%.3e em1=%.3e tag0..7= %.0f %.0f %.0f %.0f %.0f %.0f %.0f %.0f\n",
           g_maskmode, x[0], x[1], x[B_ * S_ - 1], emb[0], g_xW[0], nbad,
           g_hall[0], hbad, g_emis[0], g_emis[1],
           out[0], out[1], out[2], out[3], out[4], out[5], out[6], out[7]);
}

// ---------------------------------------------------------------------------
// launch
// ---------------------------------------------------------------------------
extern "C" void kernel_launch(void* const* d_in, const int* in_sizes, int n_in,
                              void* d_out, int out_size)
{
    // host-side binding diagnostic (shows in failure log)
    printf("HOSTDIAG n_in=%d out_size=%d sizes:", n_in, out_size);
    for (int i = 0; i < n_in; ++i) printf(" %d", in_sizes[i]);
    printf("\n");
    fflush(stdout);

    // Locate emb (unique element count) to confirm dict-order binding.
    int ei = -1;
    for (int i = 0; i < n_in; ++i)
        if (in_sizes[i] == 50001 * 256) { ei = i; break; }
    if (ei < 0) ei = 2;

    const int*  x    = (const int*)d_in[0];
    const void* mask = (ei >= 2) ? d_in[1] : nullptr;
    int have_mask    = (ei >= 2) ? 1 : 0;

    const float* emb    = (const float*)d_in[ei];
    const float* Wihf   = (const float*)d_in[ei + 1];
    const float* Whhf   = (const float*)d_in[ei + 2];
    const float* bihf   = (const float*)d_in[ei + 3];
    const float* bhhf   = (const float*)d_in[ei + 4];
    const float* Wihb   = (const float*)d_in[ei + 5];
    const float* Whhb   = (const float*)d_in[ei + 6];
    const float* bihb   = (const float*)d_in[ei + 7];
    const float* bhhb   = (const float*)d_in[ei + 8];
    const float* Wout   = (const float*)d_in[ei + 9];
    const float* bout   = (const float*)d_in[ei + 10];
    const float* trans  = (const float*)d_in[ei + 11];
    const float* startv = (const float*)d_in[ei + 12];
    const float* endv   = (const float*)d_in[ei + 13];
    float* out = (float*)d_out;

    init_kernel<<<512, 256>>>((const unsigned*)mask, have_mask);

    dim3 gg(512, 128);                // m tiles x n tiles
    gemm_simple<<<gg, 256>>>(x, emb, Wihf, Wihb);

    for (int s = 0; s < S_; ++s)
        step_kernel<<<128, 256>>>(s, Whhf, Whhb, bihf, bhhf, bihb, bhhb);

    emis_kernel<<<128, 256>>>(Wout, bout);

    viterbi_kernel<<<64, 32>>>(mask, trans, startv, endv, out);

    diag_kernel<<<1, 32>>>(x, emb, out);
}

// round 6
// speedup vs baseline: 1.2598x; 1.2598x over previous
#include <cuda_runtime.h>
#include <cuda_bf16.h>
#include <cstdint>
#include <math.h>

#define B_   64
#define S_   512
#define E_   256
#define H_   256
#define NT_  24
#define M_   (S_ * B_)   // 32768

// ---------------------------------------------------------------------------
// Device-global scratch (allocation-free rule)
// ---------------------------------------------------------------------------
__device__ float g_xW[2048ll * 32768ll];           // [n = dir*1024+gate*256+u][m = t*64+b]
__device__ float g_h[2][2][256][64];               // [dir][pingpong][unit][b]
__device__ float g_hall[512ll * 512ll * 64ll];     // [t][c = dir*256+u][b]
__device__ float g_emis[(long long)S_ * B_ * NT_]; // [t][b][tag]
__device__ unsigned g_barcnt[2];                   // per-direction barrier counters
__device__ int   g_maskmode;                       // 0=u8 1=i32 2=f32 3=bf16 4=all-true

__device__ __forceinline__ float sigm(float x) { return 1.0f / (1.0f + expf(-x)); }

__device__ __forceinline__ unsigned ld_acq(const unsigned* p) {
    unsigned v;
    asm volatile("ld.acquire.gpu.u32 %0, [%1];" : "=r"(v) : "l"(p) : "memory");
    return v;
}
__device__ __forceinline__ void red_rel_add(unsigned* p, unsigned v) {
    asm volatile("red.release.gpu.add.u32 [%0], %1;" :: "l"(p), "r"(v) : "memory");
}

__device__ __forceinline__ bool read_mask(const void* m, int i, int mode) {
    switch (mode) {
        case 0:  return ((const unsigned char*)m)[i] != 0;
        case 1:  return ((const int*)m)[i] != 0;
        case 2:  return ((const float*)m)[i] != 0.0f;
        case 3:  return ((const unsigned short*)m)[i] != 0;
        default: return true;
    }
}

// ---------------------------------------------------------------------------
// init: zero h ping-pong, reset barriers, detect mask dtype.
// ---------------------------------------------------------------------------
__global__ void init_kernel(const unsigned* __restrict__ mask_words, int have_mask)
{
    int i = blockIdx.x * 256 + threadIdx.x;
    if (i < 2 * 2 * 256 * 64) (&g_h[0][0][0][0])[i] = 0.0f;
    if (i < 2) g_barcnt[i] = 0u;
    if (i == 0) {
        // mask[0][0..3] are all True by construction (lengths >= 256).
        int mode = 4;
        if (have_mask) {
            unsigned w = mask_words[0];
            if (w == 1u)               mode = 1;
            else if (w == 0x3F800000u) mode = 2;
            else if (w == 0x3F803F80u) mode = 3;
            else                       mode = 0;
        }
        g_maskmode = mode;
    }
}

// ---------------------------------------------------------------------------
// GEMM (unchanged from passing round): xW[n][m] = Wih_row_n . emb[tok(m)]
// ---------------------------------------------------------------------------
__global__ void __launch_bounds__(256) gemm_simple(const int* __restrict__ x,
                                                   const float* __restrict__ emb,
                                                   const float* __restrict__ Wf,
                                                   const float* __restrict__ Wb)
{
    __shared__ float es[128][65];
    __shared__ float Ws[16][128];
    __shared__ int   tok[64];

    const int tid = threadIdx.x;
    const int m0  = blockIdx.x * 64;
    const int n0  = blockIdx.y * 16;
    const float* W = (n0 < 1024) ? (Wf + (size_t)n0 * E_)
                                 : (Wb + (size_t)(n0 - 1024) * E_);

    if (tid < 64) {
        int m = m0 + tid;
        int tk = x[(m & 63) * S_ + (m >> 6)];      // x[b][t], b=m&63, t=m>>6
        tok[tid] = min(max(tk, 0), 50000);
    }
    __syncthreads();

    const int j  = tid >> 6;
    const int ml = tid & 63;

    float acc[4] = {0.0f, 0.0f, 0.0f, 0.0f};

    for (int kh = 0; kh < 2; ++kh) {
        for (int idx = tid; idx < 64 * 128; idx += 256) {
            int mm = idx >> 7;
            int kk = idx & 127;
            es[kk][mm] = emb[(size_t)tok[mm] * E_ + kh * 128 + kk];
        }
        for (int idx = tid; idx < 16 * 128; idx += 256) {
            int r  = idx >> 7;
            int kk = idx & 127;
            Ws[r][kk] = W[(size_t)r * E_ + kh * 128 + kk];
        }
        __syncthreads();

        for (int kk = 0; kk < 128; ++kk) {
            float hv = es[kk][ml];
#pragma unroll
            for (int rr = 0; rr < 4; ++rr)
                acc[rr] = fmaf(Ws[j * 4 + rr][kk], hv, acc[rr]);
        }
        __syncthreads();
    }

#pragma unroll
    for (int rr = 0; rr < 4; ++rr) {
        int n = n0 + j * 4 + rr;
        g_xW[(size_t)n * M_ + m0 + ml] = acc[rr];
    }
}

// ---------------------------------------------------------------------------
// Persistent bidirectional LSTM recurrence.
// 128 blocks x 256 threads, all co-resident (33KB smem -> 1 block/SM, 1 wave).
// Block: dir = bx>>6, units us..us+3. Thread (j=tid>>6, b=tid&63) owns cell
// state c(u=us+j, b) in a register for all 512 steps. Whh slice in SMEM once.
// Math identical to the validated step_kernel:
//   gates: ((xW + hW) + bih) + bhh ; c = sigm(f)*c + sigm(i)*tanhf(g);
//   h = sigm(o)*tanhf(c)
// Per-direction grid barrier: red.release counter + ld.acquire spin.
// ---------------------------------------------------------------------------
__global__ void __launch_bounds__(256) recur_persist(const float* __restrict__ Whf,
                                                     const float* __restrict__ Whb,
                                                     const float* __restrict__ bihf,
                                                     const float* __restrict__ bhhf,
                                                     const float* __restrict__ bihb,
                                                     const float* __restrict__ bhhb)
{
    __shared__ float Whs[16][256];   // [gate*4 + jj][k]
    __shared__ float hs[64][65];     // h chunk [k_local][b]

    const int tid = threadIdx.x;
    const int dir = blockIdx.x >> 6;
    const int us  = (blockIdx.x & 63) * 4;
    const int j   = tid >> 6;
    const int b   = tid & 63;
    const int u   = us + j;

    const float* Wh  = dir ? Whb : Whf;
    const float* bih = dir ? bihb : bihf;
    const float* bhh = dir ? bhhb : bhhf;

    // stage Whh rows for these 4 units (once for all 512 steps)
    for (int idx = tid; idx < 16 * 256; idx += 256) {
        int r  = idx >> 8;           // 0..15 = gate*4 + jj
        int kk = idx & 255;
        Whs[r][kk] = Wh[(size_t)((r >> 2) * 256 + us + (r & 3)) * 256 + kk];
    }

    float bi_[4], bh_[4];
#pragma unroll
    for (int g = 0; g < 4; ++g) {
        bi_[g] = bih[g * 256 + u];
        bh_[g] = bhh[g * 256 + u];
    }

    float creg = 0.0f;
    unsigned* bar = &g_barcnt[dir];

    __syncthreads();

    for (int s = 0; s < S_; ++s) {
        const int t  = dir ? (S_ - 1 - s) : s;
        const int rb = s & 1, wbuf = rb ^ 1;

        // prefetch xW for this step (4 scattered loads, issued early)
        float xw[4];
#pragma unroll
        for (int g = 0; g < 4; ++g)
            xw[g] = g_xW[(size_t)(dir * 1024 + g * 256 + u) * M_ + t * 64 + b];

        float acc[4] = {0.0f, 0.0f, 0.0f, 0.0f};

        for (int kc = 0; kc < 4; ++kc) {
            __syncthreads();   // hs reuse protection
            for (int idx = tid; idx < 64 * 64; idx += 256) {
                int kk = idx >> 6;
                int bb = idx & 63;
                hs[kk][bb] = g_h[dir][rb][kc * 64 + kk][bb];
            }
            __syncthreads();

            for (int kk = 0; kk < 64; ++kk) {
                float hv = hs[kk][b];
#pragma unroll
                for (int g = 0; g < 4; ++g)
                    acc[g] = fmaf(Whs[g * 4 + j][kc * 64 + kk], hv, acc[g]);
            }
        }

        float gv[4];
#pragma unroll
        for (int g = 0; g < 4; ++g)
            gv[g] = ((xw[g] + acc[g]) + bi_[g]) + bh_[g];

        float c = sigm(gv[1]) * creg + sigm(gv[0]) * tanhf(gv[2]);
        float h = sigm(gv[3]) * tanhf(c);
        creg = c;

        g_h[dir][wbuf][u][b] = h;
        g_hall[((size_t)t * 512 + dir * 256 + u) * 64 + b] = h;

        // per-direction grid barrier
        __syncthreads();                    // block's writes all issued
        if (tid == 0) {
            red_rel_add(bar, 1u);           // release: orders our h stores
            unsigned target = 64u * (unsigned)(s + 1);
            while (ld_acq(bar) < target) { __nanosleep(20); }
        }
        __syncthreads();                    // rest of block waits on tid0
    }
}

// ---------------------------------------------------------------------------
// Emission: thread per (t,b). grid 128 x 256.
// ---------------------------------------------------------------------------
__global__ void __launch_bounds__(256) emis_kernel(const float* __restrict__ Wout,
                                                   const float* __restrict__ bout)
{
    const int gid = blockIdx.x * 256 + threadIdx.x;
    const int t = gid >> 6, b = gid & 63;

    float acc[NT_];
#pragma unroll
    for (int jj = 0; jj < NT_; ++jj) acc[jj] = 0.0f;

    const float* hp = g_hall + (size_t)t * 512 * 64 + b;
    for (int k = 0; k < 512; ++k) {
        float hv = hp[(size_t)k * 64];
#pragma unroll
        for (int jj = 0; jj < NT_; ++jj)
            acc[jj] = fmaf(hv, Wout[jj * 512 + k], acc[jj]);
    }

    float* op = g_emis + (size_t)(t * 64 + b) * NT_;
#pragma unroll
    for (int jj = 0; jj < NT_; ++jj) op[jj] = acc[jj] + bout[jj];
}

// ---------------------------------------------------------------------------
// Viterbi: one block per batch. FLOAT tag output (the Round-5 fix).
// ---------------------------------------------------------------------------
__global__ void viterbi_kernel(const void* __restrict__ mask,
                               const float* __restrict__ trans,
                               const float* __restrict__ startv,
                               const float* __restrict__ endv,
                               float* __restrict__ out)
{
    __shared__ float tr[24][25];
    __shared__ float sc[2][24];
    __shared__ unsigned char bp[511][24];
    __shared__ int tagseq[512];

    const int b   = blockIdx.x;
    const int tid = threadIdx.x;
    const int mode = g_maskmode;

    for (int f = tid; f < 576; f += 32) tr[f / 24][f % 24] = trans[f];
    if (tid < 24) sc[0][tid] = startv[tid] + g_emis[(size_t)b * NT_ + tid];
    __syncwarp();

    for (int t = 1; t < S_; ++t) {
        int pr = (t - 1) & 1, nx = t & 1;
        if (tid < 24) {
            float e = g_emis[((size_t)t * 64 + b) * NT_ + tid];
            float best = (sc[pr][0] + tr[0][tid]) + e;
            int bi = 0;
#pragma unroll
            for (int i = 1; i < 24; ++i) {
                float v = (sc[pr][i] + tr[i][tid]) + e;
                if (v > best) { best = v; bi = i; }
            }
            if (read_mask(mask, b * S_ + t, mode)) {
                sc[nx][tid]    = best;
                bp[t - 1][tid] = (unsigned char)bi;
            } else {
                sc[nx][tid]    = sc[pr][tid];
                bp[t - 1][tid] = (unsigned char)tid;
            }
        }
        __syncwarp();
    }

    if (tid == 0) {
        float best = sc[1][0] + endv[0];
        int bi = 0;
        for (int i = 1; i < 24; ++i) {
            float v = sc[1][i] + endv[i];
            if (v > best) { best = v; bi = i; }
        }
        int cur = bi;
        tagseq[511] = cur;
        for (int t = 511; t >= 1; --t) {
            cur = bp[t - 1][cur];
            tagseq[t - 1] = cur;
        }
    }
    __syncthreads();
    for (int t = tid; t < S_; t += 32) out[b * S_ + t] = (float)tagseq[t];
}

// ---------------------------------------------------------------------------
// launch
// ---------------------------------------------------------------------------
extern "C" void kernel_launch(void* const* d_in, const int* in_sizes, int n_in,
                              void* d_out, int out_size)
{
    // Locate emb (unique element count) to confirm dict-order binding.
    int ei = -1;
    for (int i = 0; i < n_in; ++i)
        if (in_sizes[i] == 50001 * 256) { ei = i; break; }
    if (ei < 0) ei = 2;

    const int*  x    = (const int*)d_in[0];
    const void* mask = (ei >= 2) ? d_in[1] : nullptr;
    int have_mask    = (ei >= 2) ? 1 : 0;

    const float* emb    = (const float*)d_in[ei];
    const float* Wihf   = (const float*)d_in[ei + 1];
    const float* Whhf   = (const float*)d_in[ei + 2];
    const float* bihf   = (const float*)d_in[ei + 3];
    const float* bhhf   = (const float*)d_in[ei + 4];
    const float* Wihb   = (const float*)d_in[ei + 5];
    const float* Whhb   = (const float*)d_in[ei + 6];
    const float* bihb   = (const float*)d_in[ei + 7];
    const float* bhhb   = (const float*)d_in[ei + 8];
    const float* Wout   = (const float*)d_in[ei + 9];
    const float* bout   = (const float*)d_in[ei + 10];
    const float* trans  = (const float*)d_in[ei + 11];
    const float* startv = (const float*)d_in[ei + 12];
    const float* endv   = (const float*)d_in[ei + 13];
    float* out = (float*)d_out;

    init_kernel<<<512, 256>>>((const unsigned*)mask, have_mask);

    dim3 gg(512, 128);
    gemm_simple<<<gg, 256>>>(x, emb, Wihf, Wihb);

    recur_persist<<<128, 256>>>(Whhf, Whhb, bihf, bhhf, bihb, bhhb);

    emis_kernel<<<128, 256>>>(Wout, bout);

    viterbi_kernel<<<64, 32>>>(mask, trans, startv, endv, out);
}

// round 7
// speedup vs baseline: 1.8240x; 1.4479x over previous
#include <cuda_runtime.h>
#include <cuda_bf16.h>
#include <cstdint>
#include <math.h>

#define B_   64
#define S_   512
#define E_   256
#define H_   256
#define NT_  24
#define M_   (S_ * B_)   // 32768

// ---------------------------------------------------------------------------
// Device-global scratch
// ---------------------------------------------------------------------------
__device__ float g_xW[2048ll * 32768ll];           // [n = dir*1024+gate*256+u][m = t*64+b]
__device__ float g_h[2][2][256][64];               // [dir][pingpong][unit][b]
__device__ float g_hall_t[(size_t)S_ * B_ * 512];  // [t][b][c]  (c: 0..255 fwd | 256..511 bwd)
__device__ float g_emis[(size_t)S_ * B_ * NT_];    // [t][b][tag]
__device__ unsigned g_barcnt[2];
__device__ int   g_maskmode;                       // 0=u8 1=i32 2=f32 3=bf16 4=all-true

// ---------------------------------------------------------------------------
// helpers
// ---------------------------------------------------------------------------
__device__ __forceinline__ float sigm(float x) { return 1.0f / (1.0f + expf(-x)); }

__device__ __forceinline__ unsigned ld_acq(const unsigned* p) {
    unsigned v;
    asm volatile("ld.acquire.gpu.u32 %0, [%1];" : "=r"(v) : "l"(p) : "memory");
    return v;
}
__device__ __forceinline__ void red_rel_add(unsigned* p, unsigned v) {
    asm volatile("red.release.gpu.add.u32 [%0], %1;" :: "l"(p), "r"(v) : "memory");
}
// packed fp32x2 FMA: d = a*b + d (elementwise, IEEE-exact per lane)
__device__ __forceinline__ void fma2(unsigned long long& d,
                                     unsigned long long a, unsigned long long b) {
    asm("fma.rn.f32x2 %0, %1, %2, %0;" : "+l"(d) : "l"(a), "l"(b));
}
__device__ __forceinline__ float2 up2(unsigned long long v) {
    return make_float2(__uint_as_float((unsigned)v), __uint_as_float((unsigned)(v >> 32)));
}

__device__ __forceinline__ bool read_mask(const void* m, int i, int mode) {
    switch (mode) {
        case 0:  return ((const unsigned char*)m)[i] != 0;
        case 1:  return ((const int*)m)[i] != 0;
        case 2:  return ((const float*)m)[i] != 0.0f;
        case 3:  return ((const unsigned short*)m)[i] != 0;
        default: return true;
    }
}

// ---------------------------------------------------------------------------
// init
// ---------------------------------------------------------------------------
__global__ void init_kernel(const unsigned* __restrict__ mask_words, int have_mask)
{
    int i = blockIdx.x * 256 + threadIdx.x;
    if (i < 2 * 2 * 256 * 64) (&g_h[0][0][0][0])[i] = 0.0f;
    if (i < 2) g_barcnt[i] = 0u;
    if (i == 0) {
        int mode = 4;
        if (have_mask) {
            unsigned w = mask_words[0];
            if (w == 1u)               mode = 1;
            else if (w == 0x3F800000u) mode = 2;
            else if (w == 0x3F803F80u) mode = 3;
            else                       mode = 0;
        }
        g_maskmode = mode;
    }
}

// ---------------------------------------------------------------------------
// GEMM2: xW[n][m] = Wih_row_n . emb[tok(m)]  (f32x2 packed, 128x128x8 tiles)
// 256 threads, thread tile 8 rows x 8 cols (4 f32x2 col-pairs), split +64.
// Weight smem duplicated so LDS.128 yields (a,a) broadcast packs.
// ---------------------------------------------------------------------------
__global__ void __launch_bounds__(256) gemm2(const int* __restrict__ x,
                                             const float* __restrict__ emb,
                                             const float* __restrict__ Wf,
                                             const float* __restrict__ Wb)
{
    __shared__ float Wd[8][264];   // duplicated: Wd[k][2r]=Wd[k][2r+1]=W[row r][k]
    __shared__ float Bs[8][132];   // Bs[k][col]
    __shared__ int   tok[128];

    const int tid = threadIdx.x;
    const int m0  = blockIdx.x * 128;
    const int n0  = blockIdx.y * 128;
    const float* W = (n0 < 1024) ? (Wf + (size_t)n0 * E_)
                                 : (Wb + (size_t)(n0 - 1024) * E_);

    if (tid < 128) {
        int m = m0 + tid;
        int tk = x[(m & 63) * S_ + (m >> 6)];
        tok[tid] = min(max(tk, 0), 50000);
    }
    __syncthreads();

    const int tx = tid & 15;      // col group
    const int ty = tid >> 4;      // row group
    const int srow = tid >> 1;    // staging row/col
    const int skq  = (tid & 1) * 4;

    unsigned long long acc2[8][4];
#pragma unroll
    for (int i = 0; i < 8; ++i)
#pragma unroll
        for (int p = 0; p < 4; ++p) acc2[i][p] = 0ull;

    for (int kc = 0; kc < E_; kc += 8) {
        float4 wv = *(const float4*)(W + (size_t)srow * E_ + kc + skq);
        float4 bv = *(const float4*)(emb + (size_t)tok[srow] * E_ + kc + skq);
#pragma unroll
        for (int q = 0; q < 4; ++q) {
            float wq = (&wv.x)[q];
            Wd[skq + q][2 * srow]     = wq;
            Wd[skq + q][2 * srow + 1] = wq;
            Bs[skq + q][srow]         = (&bv.x)[q];
        }
        __syncthreads();

#pragma unroll
        for (int k = 0; k < 8; ++k) {
            ulonglong2 a01 = *(const ulonglong2*)&Wd[k][2 * (ty * 4)];
            ulonglong2 a23 = *(const ulonglong2*)&Wd[k][2 * (ty * 4) + 4];
            ulonglong2 a45 = *(const ulonglong2*)&Wd[k][2 * (64 + ty * 4)];
            ulonglong2 a67 = *(const ulonglong2*)&Wd[k][2 * (64 + ty * 4) + 4];
            ulonglong2 b01 = *(const ulonglong2*)&Bs[k][tx * 4];
            ulonglong2 b23 = *(const ulonglong2*)&Bs[k][64 + tx * 4];
            unsigned long long aa[8] = {a01.x, a01.y, a23.x, a23.y,
                                        a45.x, a45.y, a67.x, a67.y};
            unsigned long long bb[4] = {b01.x, b01.y, b23.x, b23.y};
#pragma unroll
            for (int i = 0; i < 8; ++i)
#pragma unroll
                for (int p = 0; p < 4; ++p)
                    fma2(acc2[i][p], aa[i], bb[p]);
        }
        __syncthreads();
    }

#pragma unroll
    for (int i = 0; i < 8; ++i) {
        int n = n0 + ((i < 4) ? (ty * 4 + i) : (64 + ty * 4 + i - 4));
        float* dst = g_xW + (size_t)n * M_ + m0;
        float2 v0 = up2(acc2[i][0]), v1 = up2(acc2[i][1]);
        float2 v2 = up2(acc2[i][2]), v3 = up2(acc2[i][3]);
        *(float4*)(dst + tx * 4)      = make_float4(v0.x, v0.y, v1.x, v1.y);
        *(float4*)(dst + 64 + tx * 4) = make_float4(v2.x, v2.y, v3.x, v3.y);
    }
}

// ---------------------------------------------------------------------------
// Persistent BiLSTM recurrence (f32x2 inner loop).
// 128 blocks x 256 threads, co-resident. Block: dir=bx>>6, 4 units (16 rows).
// Compute thread: (rp = tid>>5: rows 2rp,2rp+1; bp = tid&31: b pair).
// Epilogue thread: (j = tid>>6 unit, b = tid&63) — identical math to round 6.
// ---------------------------------------------------------------------------
__global__ void __launch_bounds__(256) recur2(const float* __restrict__ Whf,
                                              const float* __restrict__ Whb,
                                              const float* __restrict__ bihf,
                                              const float* __restrict__ bhhf,
                                              const float* __restrict__ bihb,
                                              const float* __restrict__ bhhb)
{
    __shared__ float Wd[16][520];    // duplicated: Wd[r][2k]=Wd[r][2k+1]=Wh_row_r[k]
    __shared__ float hs[32][68];     // h chunk [k_local][b]
    __shared__ float gsum[16][66];   // staged gate dot-products

    const int tid = threadIdx.x;
    const int dir = blockIdx.x >> 6;
    const int us  = (blockIdx.x & 63) * 4;

    const float* Wh  = dir ? Whb : Whf;
    const float* bih = dir ? bihb : bihf;
    const float* bhh = dir ? bhhb : bhhf;

    // one-time: duplicated Whh slice (16 rows x 256 k)
    for (int idx = tid; idx < 16 * 256; idx += 256) {
        int r  = idx >> 8;
        int kk = idx & 255;
        float v = Wh[(size_t)((r >> 2) * 256 + us + (r & 3)) * 256 + kk];
        Wd[r][2 * kk]     = v;
        Wd[r][2 * kk + 1] = v;
    }

    // epilogue-role constants
    const int j = tid >> 6;        // unit 0..3
    const int b = tid & 63;
    const int u = us + j;
    float bi_[4], bh_[4];
#pragma unroll
    for (int g = 0; g < 4; ++g) {
        bi_[g] = bih[g * 256 + u];
        bh_[g] = bhh[g * 256 + u];
    }
    float creg = 0.0f;

    // compute-role constants
    const int rp = tid >> 5;       // row pair 0..7
    const int bp = tid & 31;       // b pair 0..31
    const int r0 = 2 * rp, r1 = 2 * rp + 1;

    unsigned* bar = &g_barcnt[dir];
    __syncthreads();

    for (int s = 0; s < S_; ++s) {
        const int t  = dir ? (S_ - 1 - s) : s;
        const int rb = s & 1, wbuf = rb ^ 1;

        // prefetch xW (epilogue role)
        float xw[4];
#pragma unroll
        for (int g = 0; g < 4; ++g)
            xw[g] = g_xW[(size_t)(dir * 1024 + g * 256 + u) * M_ + t * 64 + b];

        unsigned long long acc0 = 0ull, acc1 = 0ull;

        for (int kc = 0; kc < 8; ++kc) {            // 8 chunks of 32 k
            __syncthreads();
            // stage h chunk: 32 x 64 floats, 2 float4 per thread
#pragma unroll
            for (int q = 0; q < 2; ++q) {
                int v  = q * 256 + tid;             // 0..511 float4 ids
                int kk = v >> 4;
                int b4 = (v & 15) * 4;
                *(float4*)&hs[kk][b4] =
                    *(const float4*)&g_h[dir][rb][kc * 32 + kk][b4];
            }
            __syncthreads();

#pragma unroll
            for (int kk = 0; kk < 32; kk += 2) {
                int gk = kc * 32 + kk;
                ulonglong2 w0 = *(const ulonglong2*)&Wd[r0][2 * gk];
                ulonglong2 w1 = *(const ulonglong2*)&Wd[r1][2 * gk];
                unsigned long long h0 = *(const unsigned long long*)&hs[kk][2 * bp];
                unsigned long long h1 = *(const unsigned long long*)&hs[kk + 1][2 * bp];
                fma2(acc0, w0.x, h0);
                fma2(acc0, w0.y, h1);
                fma2(acc1, w1.x, h0);
                fma2(acc1, w1.y, h1);
            }
        }

        __syncthreads();
        *(unsigned long long*)&gsum[r0][2 * bp] = acc0;
        *(unsigned long long*)&gsum[r1][2 * bp] = acc1;
        __syncthreads();

        // epilogue (math identical to validated round-6 kernel)
        {
            float gv[4];
#pragma unroll
            for (int g = 0; g < 4; ++g)
                gv[g] = ((xw[g] + gsum[g * 4 + j][b]) + bi_[g]) + bh_[g];

            float c = sigm(gv[1]) * creg + sigm(gv[0]) * tanhf(gv[2]);
            float h = sigm(gv[3]) * tanhf(c);
            creg = c;

            g_h[dir][wbuf][u][b] = h;
            g_hall_t[((size_t)t * 64 + b) * 512 + dir * 256 + u] = h;
        }

        __syncthreads();
        if (tid == 0) {
            red_rel_add(bar, 1u);
            unsigned target = 64u * (unsigned)(s + 1);
            while (ld_acq(bar) < target) { __nanosleep(20); }
        }
        __syncthreads();
    }
}

// ---------------------------------------------------------------------------
// Emission: contiguous float4 h reads ([t][b][c] layout), Wout in 48KB smem.
// grid 256 blocks x 128 threads; thread = (t = bx*2 + tid>>6, b = tid&63).
// ---------------------------------------------------------------------------
__global__ void __launch_bounds__(128) emis2(const float* __restrict__ Wout,
                                             const float* __restrict__ bout)
{
    __shared__ float ws[24][512];    // exactly 48KB

    const int tid = threadIdx.x;
    for (int idx = tid; idx < 3072; idx += 128)
        *(float4*)&ws[0][idx * 4] = *(const float4*)&Wout[idx * 4];
    __syncthreads();

    const int t = blockIdx.x * 2 + (tid >> 6);
    const int b = tid & 63;

    float acc[NT_];
#pragma unroll
    for (int jj = 0; jj < NT_; ++jj) acc[jj] = 0.0f;

    const float* hp = g_hall_t + ((size_t)t * 64 + b) * 512;
    for (int c = 0; c < 512; c += 4) {
        float4 hv = *(const float4*)(hp + c);
#pragma unroll
        for (int jj = 0; jj < NT_; ++jj) {
            float4 w = *(const float4*)&ws[jj][c];
            acc[jj] = fmaf(hv.x, w.x, acc[jj]);
            acc[jj] = fmaf(hv.y, w.y, acc[jj]);
            acc[jj] = fmaf(hv.z, w.z, acc[jj]);
            acc[jj] = fmaf(hv.w, w.w, acc[jj]);
        }
    }

    float* op = g_emis + ((size_t)t * 64 + b) * NT_;
#pragma unroll
    for (int jj = 0; jj < NT_; ++jj) op[jj] = acc[jj] + bout[jj];
}

// ---------------------------------------------------------------------------
// Viterbi: one block per batch; mask staged to smem, e[t+1] prefetched.
// Strict-> ascending scan == jnp.argmax first-index tie-break.
// ---------------------------------------------------------------------------
__global__ void viterbi_kernel(const void* __restrict__ mask,
                               const float* __restrict__ trans,
                               const float* __restrict__ startv,
                               const float* __restrict__ endv,
                               float* __restrict__ out)
{
    __shared__ float tr[24][25];
    __shared__ float sc[2][24];
    __shared__ unsigned char bp[511][24];
    __shared__ unsigned char msk[512];
    __shared__ int tagseq[512];

    const int b   = blockIdx.x;
    const int tid = threadIdx.x;
    const int mode = g_maskmode;

    for (int f = tid; f < 576; f += 32) tr[f / 24][f % 24] = trans[f];
    for (int f = tid; f < 512; f += 32) msk[f] = read_mask(mask, b * S_ + f, mode) ? 1 : 0;
    if (tid < 24) sc[0][tid] = startv[tid] + g_emis[(size_t)b * NT_ + tid];
    __syncwarp();

    float e_cur = 0.0f;
    if (tid < 24) e_cur = g_emis[((size_t)64 + b) * NT_ + tid];   // t=1

    for (int t = 1; t < S_; ++t) {
        int pr = (t - 1) & 1, nx = t & 1;
        float e_next = 0.0f;
        if (tid < 24 && t + 1 < S_)
            e_next = g_emis[((size_t)(t + 1) * 64 + b) * NT_ + tid];
        if (tid < 24) {
            float best = (sc[pr][0] + tr[0][tid]) + e_cur;
            int bi = 0;
#pragma unroll
            for (int i = 1; i < 24; ++i) {
                float v = (sc[pr][i] + tr[i][tid]) + e_cur;
                if (v > best) { best = v; bi = i; }
            }
            if (msk[t]) {
                sc[nx][tid]    = best;
                bp[t - 1][tid] = (unsigned char)bi;
            } else {
                sc[nx][tid]    = sc[pr][tid];
                bp[t - 1][tid] = (unsigned char)tid;
            }
        }
        e_cur = e_next;
        __syncwarp();
    }

    if (tid == 0) {
        float best = sc[1][0] + endv[0];
        int bi = 0;
        for (int i = 1; i < 24; ++i) {
            float v = sc[1][i] + endv[i];
            if (v > best) { best = v; bi = i; }
        }
        int cur = bi;
        tagseq[511] = cur;
        for (int t = 511; t >= 1; --t) {
            cur = bp[t - 1][cur];
            tagseq[t - 1] = cur;
        }
    }
    __syncthreads();
    for (int t = tid; t < S_; t += 32) out[b * S_ + t] = (float)tagseq[t];
}

// ---------------------------------------------------------------------------
// launch
// ---------------------------------------------------------------------------
extern "C" void kernel_launch(void* const* d_in, const int* in_sizes, int n_in,
                              void* d_out, int out_size)
{
    int ei = -1;
    for (int i = 0; i < n_in; ++i)
        if (in_sizes[i] == 50001 * 256) { ei = i; break; }
    if (ei < 0) ei = 2;

    const int*  x    = (const int*)d_in[0];
    const void* mask = (ei >= 2) ? d_in[1] : nullptr;
    int have_mask    = (ei >= 2) ? 1 : 0;

    const float* emb    = (const float*)d_in[ei];
    const float* Wihf   = (const float*)d_in[ei + 1];
    const float* Whhf   = (const float*)d_in[ei + 2];
    const float* bihf   = (const float*)d_in[ei + 3];
    const float* bhhf   = (const float*)d_in[ei + 4];
    const float* Wihb   = (const float*)d_in[ei + 5];
    const float* Whhb   = (const float*)d_in[ei + 6];
    const float* bihb   = (const float*)d_in[ei + 7];
    const float* bhhb   = (const float*)d_in[ei + 8];
    const float* Wout   = (const float*)d_in[ei + 9];
    const float* bout   = (const float*)d_in[ei + 10];
    const float* trans  = (const float*)d_in[ei + 11];
    const float* startv = (const float*)d_in[ei + 12];
    const float* endv   = (const float*)d_in[ei + 13];
    float* out = (float*)d_out;

    init_kernel<<<512, 256>>>((const unsigned*)mask, have_mask);

    dim3 gg(M_ / 128, 2048 / 128);   // 256 x 16
    gemm2<<<gg, 256>>>(x, emb, Wihf, Wihb);

    recur2<<<128, 256>>>(Whhf, Whhb, bihf, bhhf, bihb, bhhb);

    emis2<<<256, 128>>>(Wout, bout);

    viterbi_kernel<<<64, 32>>>(mask, trans, startv, endv, out);
}

// round 8
// speedup vs baseline: 2.6842x; 1.4716x over previous
#include <cuda_runtime.h>
#include <cuda_bf16.h>
#include <cstdint>
#include <math.h>

#define B_   64
#define S_   512
#define E_   256
#define H_   256
#define NT_  24
#define M_   (S_ * B_)   // 32768

// ---------------------------------------------------------------------------
// Device-global scratch
// ---------------------------------------------------------------------------
__device__ float g_xW[2048ll * 32768ll];           // [n = dir*1024+gate*256+u][m = t*64+b]
__device__ float g_h[2][2][256][64];               // [dir][pingpong][unit][b]
__device__ float g_hall_t[(size_t)S_ * B_ * 512];  // [t][b][c]
__device__ float g_emis[(size_t)S_ * B_ * NT_];    // [t][b][tag]
__device__ unsigned g_barcnt[2];
__device__ int   g_maskmode;

// ---------------------------------------------------------------------------
// helpers
// ---------------------------------------------------------------------------
__device__ __forceinline__ float sigm(float x) { return 1.0f / (1.0f + expf(-x)); }

__device__ __forceinline__ unsigned ld_acq(const unsigned* p) {
    unsigned v;
    asm volatile("ld.acquire.gpu.u32 %0, [%1];" : "=r"(v) : "l"(p) : "memory");
    return v;
}
__device__ __forceinline__ void red_rel_add(unsigned* p, unsigned v) {
    asm volatile("red.release.gpu.add.u32 [%0], %1;" :: "l"(p), "r"(v) : "memory");
}
__device__ __forceinline__ void fma2(unsigned long long& d,
                                     unsigned long long a, unsigned long long b) {
    asm("fma.rn.f32x2 %0, %1, %2, %0;" : "+l"(d) : "l"(a), "l"(b));
}
__device__ __forceinline__ float2 up2(unsigned long long v) {
    return make_float2(__uint_as_float((unsigned)v), __uint_as_float((unsigned)(v >> 32)));
}

__device__ __forceinline__ bool read_mask(const void* m, int i, int mode) {
    switch (mode) {
        case 0:  return ((const unsigned char*)m)[i] != 0;
        case 1:  return ((const int*)m)[i] != 0;
        case 2:  return ((const float*)m)[i] != 0.0f;
        case 3:  return ((const unsigned short*)m)[i] != 0;
        default: return true;
    }
}

// ---------------------------------------------------------------------------
// init
// ---------------------------------------------------------------------------
__global__ void init_kernel(const unsigned* __restrict__ mask_words, int have_mask)
{
    int i = blockIdx.x * 256 + threadIdx.x;
    if (i < 2 * 2 * 256 * 64) (&g_h[0][0][0][0])[i] = 0.0f;
    if (i < 2) g_barcnt[i] = 0u;
    if (i == 0) {
        int mode = 4;
        if (have_mask) {
            unsigned w = mask_words[0];
            if (w == 1u)               mode = 1;
            else if (w == 0x3F800000u) mode = 2;
            else if (w == 0x3F803F80u) mode = 3;
            else                       mode = 0;
        }
        g_maskmode = mode;
    }
}

// ---------------------------------------------------------------------------
// GEMM2 (f32x2, 128x128x8 tiles) + register double-buffered staging.
// ---------------------------------------------------------------------------
__global__ void __launch_bounds__(256) gemm2(const int* __restrict__ x,
                                             const float* __restrict__ emb,
                                             const float* __restrict__ Wf,
                                             const float* __restrict__ Wb)
{
    __shared__ float Wd[8][264];   // duplicated: Wd[k][2r]=Wd[k][2r+1]=W[row r][k]
    __shared__ float Bs[8][132];   // Bs[k][col]
    __shared__ int   tok[128];

    const int tid = threadIdx.x;
    const int m0  = blockIdx.x * 128;
    const int n0  = blockIdx.y * 128;
    const float* W = (n0 < 1024) ? (Wf + (size_t)n0 * E_)
                                 : (Wb + (size_t)(n0 - 1024) * E_);

    if (tid < 128) {
        int m = m0 + tid;
        int tk = x[(m & 63) * S_ + (m >> 6)];
        tok[tid] = min(max(tk, 0), 50000);
    }
    __syncthreads();

    const int tx = tid & 15;
    const int ty = tid >> 4;
    const int srow = tid >> 1;
    const int skq  = (tid & 1) * 4;
    const float* wp = W + (size_t)srow * E_ + skq;
    const float* bp = emb + (size_t)tok[srow] * E_ + skq;

    unsigned long long acc2[8][4];
#pragma unroll
    for (int i = 0; i < 8; ++i)
#pragma unroll
        for (int p = 0; p < 4; ++p) acc2[i][p] = 0ull;

    // prologue: stage chunk 0
    {
        float4 wv = *(const float4*)(wp);
        float4 bv = *(const float4*)(bp);
#pragma unroll
        for (int q = 0; q < 4; ++q) {
            float wq = (&wv.x)[q];
            Wd[skq + q][2 * srow]     = wq;
            Wd[skq + q][2 * srow + 1] = wq;
            Bs[skq + q][srow]         = (&bv.x)[q];
        }
    }
    __syncthreads();

    for (int kc = 0; kc < E_; kc += 8) {
        // prefetch next chunk into registers (overlaps with compute)
        float4 wv, bv;
        const bool more = (kc + 8) < E_;
        if (more) {
            wv = *(const float4*)(wp + kc + 8);
            bv = *(const float4*)(bp + kc + 8);
        }

#pragma unroll
        for (int k = 0; k < 8; ++k) {
            ulonglong2 a01 = *(const ulonglong2*)&Wd[k][2 * (ty * 4)];
            ulonglong2 a23 = *(const ulonglong2*)&Wd[k][2 * (ty * 4) + 4];
            ulonglong2 a45 = *(const ulonglong2*)&Wd[k][2 * (64 + ty * 4)];
            ulonglong2 a67 = *(const ulonglong2*)&Wd[k][2 * (64 + ty * 4) + 4];
            ulonglong2 b01 = *(const ulonglong2*)&Bs[k][tx * 4];
            ulonglong2 b23 = *(const ulonglong2*)&Bs[k][64 + tx * 4];
            unsigned long long aa[8] = {a01.x, a01.y, a23.x, a23.y,
                                        a45.x, a45.y, a67.x, a67.y};
            unsigned long long bb[4] = {b01.x, b01.y, b23.x, b23.y};
#pragma unroll
            for (int i = 0; i < 8; ++i)
#pragma unroll
                for (int p = 0; p < 4; ++p)
                    fma2(acc2[i][p], aa[i], bb[p]);
        }
        __syncthreads();

        if (more) {
#pragma unroll
            for (int q = 0; q < 4; ++q) {
                float wq = (&wv.x)[q];
                Wd[skq + q][2 * srow]     = wq;
                Wd[skq + q][2 * srow + 1] = wq;
                Bs[skq + q][srow]         = (&bv.x)[q];
            }
            __syncthreads();
        }
    }

#pragma unroll
    for (int i = 0; i < 8; ++i) {
        int n = n0 + ((i < 4) ? (ty * 4 + i) : (64 + ty * 4 + i - 4));
        float* dst = g_xW + (size_t)n * M_ + m0;
        float2 v0 = up2(acc2[i][0]), v1 = up2(acc2[i][1]);
        float2 v2 = up2(acc2[i][2]), v3 = up2(acc2[i][3]);
        *(float4*)(dst + tx * 4)      = make_float4(v0.x, v0.y, v1.x, v1.y);
        *(float4*)(dst + 64 + tx * 4) = make_float4(v2.x, v2.y, v3.x, v3.y);
    }
}

// ---------------------------------------------------------------------------
// recur3: persistent BiLSTM, k-split warp mapping.
// 128 blocks x 256 threads. Block: dir, 4 units (16 gate rows).
// Warp w owns k in [32w, 32w+32); thread (w, bp) computes ALL 16 rows for its
// b-pair: h loaded once per thread via 32 coalesced LDG.64 into registers (the
// 8B load is the fma2 operand). W via broadcast LDS.128 from duplicated smem.
// Per-warp partials reduced through part[8][16][68] once per step.
// ---------------------------------------------------------------------------
__global__ void __launch_bounds__(256) recur3(const float* __restrict__ Whf,
                                              const float* __restrict__ Whb,
                                              const float* __restrict__ bihf,
                                              const float* __restrict__ bhhf,
                                              const float* __restrict__ bihb,
                                              const float* __restrict__ bhhb)
{
    __shared__ float Wd[16][520];     // duplicated: Wd[r][2k]=Wd[r][2k+1]
    __shared__ float part[8][16][68]; // per-warp partial sums [w][r][b]

    const int tid = threadIdx.x;
    const int dir = blockIdx.x >> 6;
    const int us  = (blockIdx.x & 63) * 4;

    const float* Wh  = dir ? Whb : Whf;
    const float* bih = dir ? bihb : bihf;
    const float* bhh = dir ? bhhb : bhhf;

    for (int idx = tid; idx < 16 * 256; idx += 256) {
        int r  = idx >> 8;
        int kk = idx & 255;
        float v = Wh[(size_t)((r >> 2) * 256 + us + (r & 3)) * 256 + kk];
        Wd[r][2 * kk]     = v;
        Wd[r][2 * kk + 1] = v;
    }

    // epilogue-role constants
    const int j = tid >> 6;
    const int b = tid & 63;
    const int u = us + j;
    float bi_[4], bh_[4];
#pragma unroll
    for (int g = 0; g < 4; ++g) {
        bi_[g] = bih[g * 256 + u];
        bh_[g] = bhh[g * 256 + u];
    }
    float creg = 0.0f;

    // compute-role constants
    const int w  = tid >> 5;       // warp id = k-chunk
    const int bpx = 2 * (tid & 31);// b base for this thread's pair

    unsigned* bar = &g_barcnt[dir];
    __syncthreads();

    for (int s = 0; s < S_; ++s) {
        const int t  = dir ? (S_ - 1 - s) : s;
        const int rb = s & 1, wbuf = rb ^ 1;

        // xw prefetch (epilogue role)
        float xw[4];
#pragma unroll
        for (int g = 0; g < 4; ++g)
            xw[g] = g_xW[(size_t)(dir * 1024 + g * 256 + u) * M_ + t * 64 + b];

        // h preload: 32 coalesced LDG.64 -> fma2 operands
        unsigned long long hreg[32];
#pragma unroll
        for (int kk = 0; kk < 32; ++kk)
            hreg[kk] = *(const unsigned long long*)&g_h[dir][rb][w * 32 + kk][bpx];

        unsigned long long acc[16];
#pragma unroll
        for (int r = 0; r < 16; ++r) acc[r] = 0ull;

#pragma unroll
        for (int kk = 0; kk < 32; kk += 2) {
            const int gk = w * 32 + kk;
#pragma unroll
            for (int r = 0; r < 16; ++r) {
                ulonglong2 wv = *(const ulonglong2*)&Wd[r][2 * gk];
                fma2(acc[r], wv.x, hreg[kk]);
                fma2(acc[r], wv.y, hreg[kk + 1]);
            }
        }

        // write partials
#pragma unroll
        for (int r = 0; r < 16; ++r)
            *(unsigned long long*)&part[w][r][bpx] = acc[r];
        __syncthreads();

        // epilogue: reduce 8 partials per gate row, nonlinearity, state update
        {
            float gv[4];
#pragma unroll
            for (int g = 0; g < 4; ++g) {
                int r = g * 4 + j;
                float sgm = part[0][r][b];
#pragma unroll
                for (int ww = 1; ww < 8; ++ww) sgm += part[ww][r][b];
                gv[g] = ((xw[g] + sgm) + bi_[g]) + bh_[g];
            }

            float c = sigm(gv[1]) * creg + sigm(gv[0]) * tanhf(gv[2]);
            float h = sigm(gv[3]) * tanhf(c);
            creg = c;

            g_h[dir][wbuf][u][b] = h;
            g_hall_t[((size_t)t * 64 + b) * 512 + dir * 256 + u] = h;
        }

        __syncthreads();
        if (tid == 0) {
            red_rel_add(bar, 1u);
            unsigned target = 64u * (unsigned)(s + 1);
            while (ld_acq(bar) < target) { __nanosleep(20); }
        }
        __syncthreads();
    }
}

// ---------------------------------------------------------------------------
// Emission (unchanged)
// ---------------------------------------------------------------------------
__global__ void __launch_bounds__(128) emis2(const float* __restrict__ Wout,
                                             const float* __restrict__ bout)
{
    __shared__ float ws[24][512];

    const int tid = threadIdx.x;
    for (int idx = tid; idx < 3072; idx += 128)
        *(float4*)&ws[0][idx * 4] = *(const float4*)&Wout[idx * 4];
    __syncthreads();

    const int t = blockIdx.x * 2 + (tid >> 6);
    const int b = tid & 63;

    float acc[NT_];
#pragma unroll
    for (int jj = 0; jj < NT_; ++jj) acc[jj] = 0.0f;

    const float* hp = g_hall_t + ((size_t)t * 64 + b) * 512;
    for (int c = 0; c < 512; c += 4) {
        float4 hv = *(const float4*)(hp + c);
#pragma unroll
        for (int jj = 0; jj < NT_; ++jj) {
            float4 w = *(const float4*)&ws[jj][c];
            acc[jj] = fmaf(hv.x, w.x, acc[jj]);
            acc[jj] = fmaf(hv.y, w.y, acc[jj]);
            acc[jj] = fmaf(hv.z, w.z, acc[jj]);
            acc[jj] = fmaf(hv.w, w.w, acc[jj]);
        }
    }

    float* op = g_emis + ((size_t)t * 64 + b) * NT_;
#pragma unroll
    for (int jj = 0; jj < NT_; ++jj) op[jj] = acc[jj] + bout[jj];
}

// ---------------------------------------------------------------------------
// Viterbi (unchanged)
// ---------------------------------------------------------------------------
__global__ void viterbi_kernel(const void* __restrict__ mask,
                               const float* __restrict__ trans,
                               const float* __restrict__ startv,
                               const float* __restrict__ endv,
                               float* __restrict__ out)
{
    __shared__ float tr[24][25];
    __shared__ float sc[2][24];
    __shared__ unsigned char bp[511][24];
    __shared__ unsigned char msk[512];
    __shared__ int tagseq[512];

    const int b   = blockIdx.x;
    const int tid = threadIdx.x;
    const int mode = g_maskmode;

    for (int f = tid; f < 576; f += 32) tr[f / 24][f % 24] = trans[f];
    for (int f = tid; f < 512; f += 32) msk[f] = read_mask(mask, b * S_ + f, mode) ? 1 : 0;
    if (tid < 24) sc[0][tid] = startv[tid] + g_emis[(size_t)b * NT_ + tid];
    __syncwarp();

    float e_cur = 0.0f;
    if (tid < 24) e_cur = g_emis[((size_t)64 + b) * NT_ + tid];

    for (int t = 1; t < S_; ++t) {
        int pr = (t - 1) & 1, nx = t & 1;
        float e_next = 0.0f;
        if (tid < 24 && t + 1 < S_)
            e_next = g_emis[((size_t)(t + 1) * 64 + b) * NT_ + tid];
        if (tid < 24) {
            float best = (sc[pr][0] + tr[0][tid]) + e_cur;
            int bi = 0;
#pragma unroll
            for (int i = 1; i < 24; ++i) {
                float v = (sc[pr][i] + tr[i][tid]) + e_cur;
                if (v > best) { best = v; bi = i; }
            }
            if (msk[t]) {
                sc[nx][tid]    = best;
                bp[t - 1][tid] = (unsigned char)bi;
            } else {
                sc[nx][tid]    = sc[pr][tid];
                bp[t - 1][tid] = (unsigned char)tid;
            }
        }
        e_cur = e_next;
        __syncwarp();
    }

    if (tid == 0) {
        float best = sc[1][0] + endv[0];
        int bi = 0;
        for (int i = 1; i < 24; ++i) {
            float v = sc[1][i] + endv[i];
            if (v > best) { best = v; bi = i; }
        }
        int cur = bi;
        tagseq[511] = cur;
        for (int t = 511; t >= 1; --t) {
            cur = bp[t - 1][cur];
            tagseq[t - 1] = cur;
        }
    }
    __syncthreads();
    for (int t = tid; t < S_; t += 32) out[b * S_ + t] = (float)tagseq[t];
}

// ---------------------------------------------------------------------------
// launch
// ---------------------------------------------------------------------------
extern "C" void kernel_launch(void* const* d_in, const int* in_sizes, int n_in,
                              void* d_out, int out_size)
{
    int ei = -1;
    for (int i = 0; i < n_in; ++i)
        if (in_sizes[i] == 50001 * 256) { ei = i; break; }
    if (ei < 0) ei = 2;

    const int*  x    = (const int*)d_in[0];
    const void* mask = (ei >= 2) ? d_in[1] : nullptr;
    int have_mask    = (ei >= 2) ? 1 : 0;

    const float* emb    = (const float*)d_in[ei];
    const float* Wihf   = (const float*)d_in[ei + 1];
    const float* Whhf   = (const float*)d_in[ei + 2];
    const float* bihf   = (const float*)d_in[ei + 3];
    const float* bhhf   = (const float*)d_in[ei + 4];
    const float* Wihb   = (const float*)d_in[ei + 5];
    const float* Whhb   = (const float*)d_in[ei + 6];
    const float* bihb   = (const float*)d_in[ei + 7];
    const float* bhhb   = (const float*)d_in[ei + 8];
    const float* Wout   = (const float*)d_in[ei + 9];
    const float* bout   = (const float*)d_in[ei + 10];
    const float* trans  = (const float*)d_in[ei + 11];
    const float* startv = (const float*)d_in[ei + 12];
    const float* endv   = (const float*)d_in[ei + 13];
    float* out = (float*)d_out;

    init_kernel<<<512, 256>>>((const unsigned*)mask, have_mask);

    dim3 gg(M_ / 128, 2048 / 128);
    gemm2<<<gg, 256>>>(x, emb, Wihf, Wihb);

    recur3<<<128, 256>>>(Whhf, Whhb, bihf, bhhf, bihb, bhhb);

    emis2<<<256, 128>>>(Wout, bout);

    viterbi_kernel<<<64, 32>>>(mask, trans, startv, endv, out);
}